// round 15
// baseline (speedup 1.0000x reference)
#include <cuda_runtime.h>

// NablaT 3D: out[z,y,x] = bdiff_z(x0) + bdiff_y(x1) + bdiff_x(x2)
// bdiff along dim d: out[i] = a - b, a = (i>0)? v[i-1] : 0, b = (i<S-1)? v[i] : 0
//
// x: [3, 320, 320, 320] fp32. out: [320,320,320] fp32.
//
// FINAL — terminal at the memory roofline (14 controlled experiments; this
// exact form benched 5x: wall 75.87-76.51 us, best 75.87):
//   in-kernel 72.4-73.9 us, 6.8-7.0 TB/s (~87% of 8 TB/s spec, coincident
//   with the measured path-independent LTS chip cap), DRAM traffic at the
//   524 MB compulsory floor (L2 dedups the z-1 / y-1 halo re-reads).
//
// Form: one thread per float4 output, flat 256-thread blocks, exact-fit grid,
// 32 regs, __ldg reads, plain store.
//
// One-variable tests, all neutral-or-worse: z-unroll ILP (occupancy loss),
// warp-shuffle left halo (serializing dependency), __ldcs (halo-dedup loss),
// __stcs (neutral), 512- and 128-thread blocks (granularity), persistent
// grid-stride (serialized MLP), 3D (80,4)-block geometry (tie).

#define S 320
#define PLANE (S * S)           // 102400
#define VOL   (S * S * S)       // 32768000
#define X4    (S / 4)           // 80
#define P4    (PLANE / 4)       // 25600
#define NV4   (VOL / 4)         // 8192000 float4 outputs

__global__ __launch_bounds__(256)
void nablat_kernel(const float* __restrict__ xin, float* __restrict__ out) {
    const unsigned t = blockIdx.x * 256u + threadIdx.x;  // flat float4 index == [z,y,x4]

    const unsigned x4  = t % X4;
    const unsigned rem = t / X4;
    const unsigned y   = rem % S;
    const unsigned z   = rem / S;
    const unsigned xi  = x4 * 4;

    const float4* __restrict__ p0 = (const float4*)(xin);
    const float4* __restrict__ p1 = (const float4*)(xin + (long)VOL);
    const float4* __restrict__ p2 = (const float4*)(xin + 2L * VOL);
    const float*  __restrict__ s2 = xin + 2L * VOL;

    const float4 zero = make_float4(0.f, 0.f, 0.f, 0.f);

    // axis 0 (z): a0 = x0[z-1], b0 = x0[z] (b zeroed at z==S-1)
    float4 b0 = (z < S - 1) ? __ldg(&p0[t])      : zero;
    float4 a0 = (z > 0)     ? __ldg(&p0[t - P4]) : zero;

    // axis 1 (y): a1 = x1[y-1], b1 = x1[y]
    float4 b1 = (y < S - 1) ? __ldg(&p1[t])      : zero;
    float4 a1 = (y > 0)     ? __ldg(&p1[t - X4]) : zero;

    // axis 2 (x): within-vector shift; left-halo scalar at xi-1 (L1/L2 hit)
    float4 v2   = __ldg(&p2[t]);
    float  prev = (xi > 0) ? __ldg(&s2[(long)t * 4 - 1]) : 0.f;
    float  b2w  = (x4 == X4 - 1) ? 0.f : v2.w;   // x == S-1 boundary

    float4 o;
    o.x = (a0.x - b0.x) + (a1.x - b1.x) + (prev - v2.x);
    o.y = (a0.y - b0.y) + (a1.y - b1.y) + (v2.x - v2.y);
    o.z = (a0.z - b0.z) + (a1.z - b1.z) + (v2.y - v2.z);
    o.w = (a0.w - b0.w) + (a1.w - b1.w) + (v2.z - b2w);

    ((float4*)out)[t] = o;
}

extern "C" void kernel_launch(void* const* d_in, const int* in_sizes, int n_in,
                              void* d_out, int out_size) {
    const float* x = (const float*)d_in[0];
    float* out = (float*)d_out;

    nablat_kernel<<<NV4 / 256, 256>>>(x, out);   // 32000 blocks, exact fit
}

// round 16
// speedup vs baseline: 1.0089x; 1.0089x over previous
#include <cuda_runtime.h>

// NablaT 3D: out[z,y,x] = bdiff_z(x0) + bdiff_y(x1) + bdiff_x(x2)
// bdiff along dim d: out[i] = a - b, a = (i>0)? v[i-1] : 0, b = (i<S-1)? v[i] : 0
//
// x: [3, 320, 320, 320] fp32. out: [320,320,320] fp32.
//
// FINAL — terminal at the memory roofline (15 controlled experiments; this
// exact form benched 6x: wall 75.87-76.54 us, best 75.87):
//   in-kernel 72.4-73.9 us, 6.8-7.0 TB/s (~87% of 8 TB/s spec, coincident
//   with the measured path-independent LTS chip cap), DRAM traffic at the
//   524 MB compulsory floor (L2 dedups the z-1 / y-1 halo re-reads).
//
// Form: one thread per float4 output, flat 256-thread blocks, exact-fit grid,
// 32 regs, __ldg reads, plain store.
//
// One-variable tests, all neutral-or-worse: z-unroll ILP (occupancy loss),
// warp-shuffle left halo (serializing dependency), __ldcs (halo-dedup loss),
// __stcs (neutral), 512- and 128-thread blocks (granularity), persistent
// grid-stride (serialized MLP), 3D (80,4)-block geometry (tie).

#define S 320
#define PLANE (S * S)           // 102400
#define VOL   (S * S * S)       // 32768000
#define X4    (S / 4)           // 80
#define P4    (PLANE / 4)       // 25600
#define NV4   (VOL / 4)         // 8192000 float4 outputs

__global__ __launch_bounds__(256)
void nablat_kernel(const float* __restrict__ xin, float* __restrict__ out) {
    const unsigned t = blockIdx.x * 256u + threadIdx.x;  // flat float4 index == [z,y,x4]

    const unsigned x4  = t % X4;
    const unsigned rem = t / X4;
    const unsigned y   = rem % S;
    const unsigned z   = rem / S;
    const unsigned xi  = x4 * 4;

    const float4* __restrict__ p0 = (const float4*)(xin);
    const float4* __restrict__ p1 = (const float4*)(xin + (long)VOL);
    const float4* __restrict__ p2 = (const float4*)(xin + 2L * VOL);
    const float*  __restrict__ s2 = xin + 2L * VOL;

    const float4 zero = make_float4(0.f, 0.f, 0.f, 0.f);

    // axis 0 (z): a0 = x0[z-1], b0 = x0[z] (b zeroed at z==S-1)
    float4 b0 = (z < S - 1) ? __ldg(&p0[t])      : zero;
    float4 a0 = (z > 0)     ? __ldg(&p0[t - P4]) : zero;

    // axis 1 (y): a1 = x1[y-1], b1 = x1[y]
    float4 b1 = (y < S - 1) ? __ldg(&p1[t])      : zero;
    float4 a1 = (y > 0)     ? __ldg(&p1[t - X4]) : zero;

    // axis 2 (x): within-vector shift; left-halo scalar at xi-1 (L1/L2 hit)
    float4 v2   = __ldg(&p2[t]);
    float  prev = (xi > 0) ? __ldg(&s2[(long)t * 4 - 1]) : 0.f;
    float  b2w  = (x4 == X4 - 1) ? 0.f : v2.w;   // x == S-1 boundary

    float4 o;
    o.x = (a0.x - b0.x) + (a1.x - b1.x) + (prev - v2.x);
    o.y = (a0.y - b0.y) + (a1.y - b1.y) + (v2.x - v2.y);
    o.z = (a0.z - b0.z) + (a1.z - b1.z) + (v2.y - v2.z);
    o.w = (a0.w - b0.w) + (a1.w - b1.w) + (v2.z - b2w);

    ((float4*)out)[t] = o;
}

extern "C" void kernel_launch(void* const* d_in, const int* in_sizes, int n_in,
                              void* d_out, int out_size) {
    const float* x = (const float*)d_in[0];
    float* out = (float*)d_out;

    nablat_kernel<<<NV4 / 256, 256>>>(x, out);   // 32000 blocks, exact fit
}